// round 12
// baseline (speedup 1.0000x reference)
#include <cuda_runtime.h>
#include <cstdint>

// FactorGNN fused pipeline (dead attention branch removed).
//   A = supports, A[j,j] = (diag==0 ? 1 : diag)
//   deg[j] = sum_i A[i,j];  dinv = deg>0 ? rsqrt(deg) : 0
//   M[i,c] = dinv[i] * (x[b,i,:] @ W_gcn)      c = b*16+o  (64 cols)
//   C[j,c] = sum_i supports[i,j] * M[i,c]      (mma.sync tf32 3-term split, split-K=4)
//   g      = relu(dinv[j]*(C + corr[j]*M[j,c]) + b_gcn)
//   out    = g.reshape(.,160) @ W_out + b_out
//
// GEMM mapping: D[m=c(64), n=j] = A(M^T, row-major) x B(S, col-major-as-is).
// tf32 m16n8k8 fragments are single-element -> no transpose/packing anywhere.

#define NF     10240
#define NB     4
#define NN     1024
#define FF     10
#define DD     16
#define DOUTC  16
#define NCOL   64
#define ROWCH  40
#define KSPLIT 4
#define KCHUNK 2560               // 4*2560 = 10240
#define NSTG   (KCHUNK/32)        // 80 stages of 32 rows
#define NSTEPS (KCHUNK/8)         // 320 k8-steps per chunk

// Scratch (static device globals: allocation-free per harness rules)
__device__ float g_M  [NF * NCOL];          // M[i][c] (for k_out corr term)
__device__ float g_Ahi[NF * NCOL];          // tf32(M)[i][c'],  c' = (c&15)*4 + (c>>4)
__device__ float g_Alo[NF * NCOL];          // tf32(M - hi)[i][c']
__device__ float g_C[KSPLIT][NF * NCOL];    // split-K partials, [j][c]
__device__ float g_degpart[ROWCH * NF];
__device__ float g_dinv[NF];
__device__ float g_corr[NF];

// ---- helpers ----
static __device__ __forceinline__ uint32_t f2tf32u(float x) {
    uint32_t u;
    asm("cvt.rna.tf32.f32 %0, %1;" : "=r"(u) : "f"(x));
    return u;
}
static __device__ __forceinline__ void mma8(float* d, const uint32_t* a,
                                            uint32_t b0, uint32_t b1) {
    asm volatile(
        "mma.sync.aligned.m16n8k8.row.col.f32.tf32.tf32.f32 "
        "{%0,%1,%2,%3}, {%4,%5,%6,%7}, {%8,%9}, {%0,%1,%2,%3};"
        : "+f"(d[0]), "+f"(d[1]), "+f"(d[2]), "+f"(d[3])
        : "r"(a[0]), "r"(a[1]), "r"(a[2]), "r"(a[3]), "r"(b0), "r"(b1));
}
static __device__ __forceinline__ void cpasync16(uint32_t saddr, const void* gptr) {
    asm volatile("cp.async.cg.shared.global [%0], [%1], 16;"
                 :: "r"(saddr), "l"(gptr));
}
static __device__ __forceinline__ void cpasync_commit() {
    asm volatile("cp.async.commit_group;");
}
template <int N>
static __device__ __forceinline__ void cpasync_wait() {
    asm volatile("cp.async.wait_group %0;" :: "n"(N));
}

// K1: partial column sums of supports (float4 lanes, HBM-bound)
__global__ void k_degpart(const float* __restrict__ S) {
    int j4 = blockIdx.x * 256 + threadIdx.x;
    int r0 = blockIdx.y * 256;
    const float4* p = (const float4*)S + (size_t)r0 * (NF / 4) + j4;
    float4 s = make_float4(0.f, 0.f, 0.f, 0.f);
#pragma unroll 8
    for (int r = 0; r < 256; r++) {
        float4 v = __ldcs(p + (size_t)r * (NF / 4));
        s.x += v.x; s.y += v.y; s.z += v.z; s.w += v.w;
    }
    ((float4*)g_degpart)[(size_t)blockIdx.y * (NF / 4) + j4] = s;
}

// K2: reduce partials, self-loop fix, produce dinv & corr
__global__ void k_finalize(const float* __restrict__ S) {
    int j = blockIdx.x * 256 + threadIdx.x;
    float s = 0.f;
#pragma unroll
    for (int p = 0; p < ROWCH; p++) s += g_degpart[p * NF + j];
    float diag = S[(size_t)j * NF + j];
    float corr = (diag == 0.f) ? 1.f : 0.f;
    float deg  = s + corr;
    g_dinv[j] = (deg > 0.f) ? rsqrtf(deg) : 0.f;
    g_corr[j] = corr;
}

// K3: M = dinv[i]*(x@W_gcn); emit g_M and tf32 hi/lo in c-permuted layout.
__global__ void k_hs(const float* __restrict__ x, const float* __restrict__ Wg) {
    __shared__ float sW[DD * DOUTC];
    if (threadIdx.x < DD * DOUTC) sW[threadIdx.x] = Wg[threadIdx.x];
    __syncthreads();
    int g = blockIdx.x * 256 + threadIdx.x;
    int o = g & 15;
    int rest = g >> 4;
    int i = rest % NF;
    int b = rest / NF;
    const float* xr = x + ((size_t)b * NF + i) * DD;
    float h = 0.f;
#pragma unroll
    for (int d = 0; d < DD; d++) h = fmaf(xr[d], sW[d * DOUTC + o], h);
    float m = g_dinv[i] * h;
    g_M[i * NCOL + b * DOUTC + o] = m;
    int cp = o * 4 + b;                      // c' permute
    uint32_t hu = f2tf32u(m);
    float hf = __uint_as_float(hu);
    uint32_t lu = f2tf32u(m - hf);
    g_Ahi[i * NCOL + cp] = hf;
    g_Alo[i * NCOL + cp] = __uint_as_float(lu);
}

// K4: tensor-core GEMM via mma.sync tf32.
// CTA: j-tile 128 (8 warps x 16 j), c = 64 (4 m-tiles), chunk 2560.
// Warp: 4 m-tiles x 2 n-tiles, 3 mmas each = 24 HMMA / k8-step.
// A (M^T hi/lo): smem stages (cp.async, 16KB/stage, double buffer).
// B (S): GMEM-direct, register ring depth 2 (gap 2 steps > DRAM latency).
__global__ __launch_bounds__(256, 2) void k_gemm(const float* __restrict__ S) {
    __shared__ alignas(16) float sA[2][2][32 * NCOL];   // [buf][hi/lo][i][c'] 32KB

    const int tx = threadIdx.x;
    const int wid = tx >> 5, lane = tx & 31;
    const int gid = lane >> 2, tg = lane & 3;
    const int jw = blockIdx.x * 128 + wid * 16;
    const int ks = blockIdx.y;
    const int i0 = ks * KCHUNK;

    float acc[4][2][4];
#pragma unroll
    for (int mt = 0; mt < 4; mt++)
#pragma unroll
        for (int nt = 0; nt < 2; nt++)
#pragma unroll
            for (int q = 0; q < 4; q++) acc[mt][nt][q] = 0.f;

    // B: per-thread base (row i0+tg, col jw+gid); offsets +4*NF (b1), +8 (nt1)
    const float* Sb = S + (size_t)(i0 + tg) * NF + jw + gid;
    float braw[2][4];
#pragma unroll
    for (int s = 0; s < 2; s++) {
        const float* p = Sb + (size_t)s * 8 * NF;
        braw[s][0] = __ldcs(p);
        braw[s][1] = __ldcs(p + 4 * NF);
        braw[s][2] = __ldcs(p + 8);
        braw[s][3] = __ldcs(p + 4 * NF + 8);
    }
    const float* Spf = Sb + (size_t)16 * NF;     // prefetch ptr (step 2)

    // A staging
    const float4* Ah4 = (const float4*)g_Ahi;
    const float4* Al4 = (const float4*)g_Alo;
    uint32_t sa[2];
    sa[0] = (uint32_t)__cvta_generic_to_shared(&sA[0][0][0]);
    sa[1] = (uint32_t)__cvta_generic_to_shared(&sA[1][0][0]);
    // stage layout inside buf: hi at +0, lo at +8KB (=512 f4)
    {   // prologue: stage 0 -> buf 0
        size_t base = (size_t)i0 * (NCOL / 4);
        cpasync16(sa[0] + tx * 16,              Ah4 + base + tx);
        cpasync16(sa[0] + (tx + 256) * 16,      Ah4 + base + tx + 256);
        cpasync16(sa[0] + 8192 + tx * 16,       Al4 + base + tx);
        cpasync16(sa[0] + 8192 + (tx + 256) * 16, Al4 + base + tx + 256);
        cpasync_commit();
    }

    for (int t = 0; t < NSTG; ++t) {
        const int buf = t & 1;
        if (t + 1 < NSTG) {
            size_t base = (size_t)(i0 + (t + 1) * 32) * (NCOL / 4);
            uint32_t d = sa[buf ^ 1];
            cpasync16(d + tx * 16,                Ah4 + base + tx);
            cpasync16(d + (tx + 256) * 16,        Ah4 + base + tx + 256);
            cpasync16(d + 8192 + tx * 16,         Al4 + base + tx);
            cpasync16(d + 8192 + (tx + 256) * 16, Al4 + base + tx + 256);
            cpasync_commit();
            cpasync_wait<1>();
        } else {
            cpasync_wait<0>();
        }
        __syncthreads();

#pragma unroll
        for (int k8 = 0; k8 < 4; ++k8) {
            const int s = t * 4 + k8;
            float rb0 = braw[s & 1][0], rb1 = braw[s & 1][1];
            float rb2 = braw[s & 1][2], rb3 = braw[s & 1][3];
            // prefetch step s+2 into the slot just freed
            if (s + 2 < NSTEPS) {
                braw[s & 1][0] = __ldcs(Spf);
                braw[s & 1][1] = __ldcs(Spf + 4 * NF);
                braw[s & 1][2] = __ldcs(Spf + 8);
                braw[s & 1][3] = __ldcs(Spf + 4 * NF + 8);
            }
            Spf += (size_t)8 * NF;

            // A fragments: 8x LDS128 (hi/lo x 4 classes), m-tiles packed in lanes
            const float* hb = &sA[buf][0][(k8 * 8 + tg) * NCOL];
            const float* lb = &sA[buf][1][(k8 * 8 + tg) * NCOL];
            uint4 aH0 = *(const uint4*)(hb + gid * 4);
            uint4 aH1 = *(const uint4*)(hb + (gid + 8) * 4);
            uint4 aH2 = *(const uint4*)(hb + 4 * NCOL + gid * 4);
            uint4 aH3 = *(const uint4*)(hb + 4 * NCOL + (gid + 8) * 4);
            uint4 aL0 = *(const uint4*)(lb + gid * 4);
            uint4 aL1 = *(const uint4*)(lb + (gid + 8) * 4);
            uint4 aL2 = *(const uint4*)(lb + 4 * NCOL + gid * 4);
            uint4 aL3 = *(const uint4*)(lb + 4 * NCOL + (gid + 8) * 4);

            // B hi/lo conversion
            uint32_t bh[2][2], bl[2][2];
            bh[0][0] = f2tf32u(rb0);
            bl[0][0] = f2tf32u(rb0 - __uint_as_float(bh[0][0]));
            bh[0][1] = f2tf32u(rb1);
            bl[0][1] = f2tf32u(rb1 - __uint_as_float(bh[0][1]));
            bh[1][0] = f2tf32u(rb2);
            bl[1][0] = f2tf32u(rb2 - __uint_as_float(bh[1][0]));
            bh[1][1] = f2tf32u(rb3);
            bl[1][1] = f2tf32u(rb3 - __uint_as_float(bh[1][1]));

            const uint32_t* h0 = &aH0.x; const uint32_t* h1 = &aH1.x;
            const uint32_t* h2 = &aH2.x; const uint32_t* h3 = &aH3.x;
            const uint32_t* l0 = &aL0.x; const uint32_t* l1 = &aL1.x;
            const uint32_t* l2 = &aL2.x; const uint32_t* l3 = &aL3.x;
#pragma unroll
            for (int mt = 0; mt < 4; mt++) {
                uint32_t AH[4] = {h0[mt], h1[mt], h2[mt], h3[mt]};
                uint32_t AL[4] = {l0[mt], l1[mt], l2[mt], l3[mt]};
#pragma unroll
                for (int nt = 0; nt < 2; nt++) {
                    mma8(acc[mt][nt], AH, bh[nt][0], bh[nt][1]);
                    mma8(acc[mt][nt], AL, bh[nt][0], bh[nt][1]);
                    mma8(acc[mt][nt], AH, bl[nt][0], bl[nt][1]);
                }
            }
        }
        __syncthreads();
    }

    // write split-K partials: D[m=c][n=j] -> g_C[ks][j][c]
#pragma unroll
    for (int mt = 0; mt < 4; mt++) {
#pragma unroll
        for (int nt = 0; nt < 2; nt++) {
            int ja = jw + nt * 8 + tg * 2;
            int ca = mt * 16 + gid;
            float* Cp = g_C[ks];
            Cp[(size_t)ja * NCOL + ca]           = acc[mt][nt][0];
            Cp[(size_t)(ja + 1) * NCOL + ca]     = acc[mt][nt][1];
            Cp[(size_t)ja * NCOL + ca + 8]       = acc[mt][nt][2];
            Cp[(size_t)(ja + 1) * NCOL + ca + 8] = acc[mt][nt][3];
        }
    }
}

// K5: epilogue (sum split-K, diag corr, dinv[j], bias, relu) + output GEMM 160x16
__global__ void k_out(const float* __restrict__ Wout, const float* __restrict__ bgcn,
                      const float* __restrict__ bout, float* __restrict__ out) {
    __shared__ float sW[FF * DOUTC * DOUTC];
    __shared__ float sg[8][FF * DOUTC];
    __shared__ float sbg[DOUTC], sbo[DOUTC];
    const int tx = threadIdx.x;
    for (int i = tx; i < FF * DOUTC * DOUTC; i += 128) sW[i] = Wout[i];
    if (tx < DOUTC) { sbg[tx] = bgcn[tx]; sbo[tx] = bout[tx]; }
    __syncthreads();

    const int r = tx >> 4, o = tx & 15;
    const int gr = blockIdx.x * 8 + r;          // (b,n) flat, 0..4095
    const int b = gr >> 10, n = gr & 1023;

#pragma unroll
    for (int f = 0; f < FF; f++) {
        const int j = n * FF + f;
        const int cidx = j * NCOL + b * DOUTC + o;
        float v = 0.f;
#pragma unroll
        for (int s = 0; s < KSPLIT; s++) v += g_C[s][cidx];
        v += g_corr[j] * g_M[cidx];
        v = g_dinv[j] * v + sbg[o];
        sg[r][f * DOUTC + o] = fmaxf(v, 0.f);
    }
    __syncthreads();

    float s = sbo[o];
#pragma unroll
    for (int k = 0; k < FF * DOUTC; k++) s = fmaf(sg[r][k], sW[k * DOUTC + o], s);
    out[(size_t)gr * DOUTC + o] = s;
}

extern "C" void kernel_launch(void* const* d_in, const int* in_sizes, int n_in,
                              void* d_out, int out_size) {
    // metadata order: x, factor_embeddings, grid_embeddings, supports,
    //                 ln_gamma, ln_beta, W_gcn, b_gcn, W_out, b_out
    const float* x  = (const float*)d_in[0];
    const float* S  = (const float*)d_in[3];
    const float* Wg = (const float*)d_in[6];
    const float* bg = (const float*)d_in[7];
    const float* Wo = (const float*)d_in[8];
    const float* bo = (const float*)d_in[9];
    float* out = (float*)d_out;

    k_degpart<<<dim3(NF / 1024, ROWCH), 256>>>(S);
    k_finalize<<<NF / 256, 256>>>(S);
    k_hs<<<(NB * NF * DOUTC) / 256, 256>>>(x, Wg);
    k_gemm<<<dim3(NF / 128, KSPLIT), 256>>>(S);
    k_out<<<(NB * NN) / 8, 128>>>(Wo, bg, bo, out);
}